// round 14
// baseline (speedup 1.0000x reference)
#include <cuda_runtime.h>
#include <cstdint>
#include <cmath>

// Problem dims (fixed)
#define B_ 4
#define L_ 2048
#define D_ 2048
#define M_ (B_*L_)          // 8192 tokens
#define NSEG 16
#define SEGLEN (L_/NSEG)    // 128
#define NCHUNK (D_/256)     // 8 channel chunks
#define NFLAGS (B_*NCHUNK*NSEG)   // 512

// ---------------- int8 GEMM tiling (R6 config: proven best, tensor-rate-limited) ----------------
#define BM 128
#define BN 128
#define BK 128
#define KT (D_/BK)          // 16
#define NSTAGE 3
#define SROW 144            // 128 data bytes + 16 pad (conflict-free ldsm rows)
#define A_ST_BYTES (BM*SROW)                    // 18432
#define STAGE_BYTES (2*A_ST_BYTES)              // 36864
#define SMEM_G (NSTAGE*STAGE_BYTES)             // 110592 -> 2 CTAs/SM

// ------------------------- scratch (static device globals) -------------------------
__device__ __align__(16) int8_t g_xq[(size_t)M_*D_];
__device__ float  g_xsc[M_];
__device__ __align__(16) int8_t g_wq[4][(size_t)D_*D_];
__device__ float  g_wpart[4][2048];
__device__ float  g_wscale[4];
__device__ float  g_ilin[(size_t)M_*D_];
__device__ float  g_flin[(size_t)M_*D_];
__device__ float  g_glin[(size_t)M_*D_];
__device__ float  g_ov  [(size_t)M_*D_];
__device__ __align__(16) int8_t g_yq[(size_t)M_*D_];
__device__ float  g_ysc[M_];
__device__ float  g_carryInc[NSEG][B_*D_];     // inclusive carries per segment
__device__ int    g_flag[NFLAGS];              // lookback ready flags (zeroed each run)

// ------------------------- helpers -------------------------
__device__ __forceinline__ float block_reduce_sum(float v, float* red) {
    int tid = threadIdx.x;
    red[tid] = v; __syncthreads();
    #pragma unroll
    for (int s = 128; s > 0; s >>= 1) {
        if (tid < s) red[tid] += red[tid + s];
        __syncthreads();
    }
    float r = red[0]; __syncthreads();
    return r;
}
__device__ __forceinline__ float block_reduce_max(float v, float* red) {
    int tid = threadIdx.x;
    red[tid] = v; __syncthreads();
    #pragma unroll
    for (int s = 128; s > 0; s >>= 1) {
        if (tid < s) red[tid] = fmaxf(red[tid], red[tid + s]);
        __syncthreads();
    }
    float r = red[0]; __syncthreads();
    return r;
}
__device__ __forceinline__ float sigmoidf_(float x) { return 1.f / (1.f + expf(-x)); }

__device__ __forceinline__ void cp16(void* smem, const void* gmem) {
    uint32_t d = (uint32_t)__cvta_generic_to_shared(smem);
    asm volatile("cp.async.cg.shared.global [%0], [%1], 16;\n" :: "r"(d), "l"(gmem));
}
__device__ __forceinline__ void ldsm_x4(uint32_t& r0, uint32_t& r1, uint32_t& r2, uint32_t& r3, uint32_t addr) {
    asm volatile("ldmatrix.sync.aligned.m8n8.x4.shared.b16 {%0,%1,%2,%3}, [%4];\n"
                 : "=r"(r0), "=r"(r1), "=r"(r2), "=r"(r3) : "r"(addr));
}

// ------------------------- 1) weight |.| partial reduction + flag reset -------------------------
__global__ void wabs_partial_kernel(const float* __restrict__ w0, const float* __restrict__ w1,
                                    const float* __restrict__ w2, const float* __restrict__ w3) {
    __shared__ float red[256];
    if (blockIdx.x == 0 && blockIdx.y == 0) {
        g_flag[threadIdx.x] = 0;
        g_flag[threadIdx.x + 256] = 0;
    }
    const float* w = (blockIdx.y == 0) ? w0 : (blockIdx.y == 1) ? w1 : (blockIdx.y == 2) ? w2 : w3;
    size_t base = (size_t)blockIdx.x * 2048 + threadIdx.x;
    float s = 0.f;
    #pragma unroll
    for (int k = 0; k < 8; k++) s += fabsf(w[base + k * 256]);
    float tot = block_reduce_sum(s, red);
    if (threadIdx.x == 0) g_wpart[blockIdx.y][blockIdx.x] = tot;
}

// ------------------------- 2) fused quant: x rows + all weights (wscale reduced inline) -------------------------
__global__ void quant_all_kernel(const float* __restrict__ x,
                                 const float* __restrict__ w0, const float* __restrict__ w1,
                                 const float* __restrict__ w2, const float* __restrict__ w3) {
    __shared__ float red[256];
    if (blockIdx.x < M_) {
        int t = blockIdx.x;
        const float* row = x + (size_t)t * D_;
        float v[8];
        float amax = 0.f;
        #pragma unroll
        for (int k = 0; k < 8; k++) {
            v[k] = row[threadIdx.x + k * 256];
            amax = fmaxf(amax, fabsf(v[k]));
        }
        amax = block_reduce_max(amax, red);
        amax = fmaxf(amax, 1e-5f);
        float s = 127.f / amax;
        if (threadIdx.x == 0) g_xsc[t] = amax / 127.f;
        int8_t* q = g_xq + (size_t)t * D_;
        #pragma unroll
        for (int k = 0; k < 8; k++) {
            float r = rintf(v[k] * s);
            r = fminf(fmaxf(r, -128.f), 127.f);
            q[threadIdx.x + k * 256] = (int8_t)r;
        }
    } else {
        int id = blockIdx.x - M_;
        int w_idx = id >> 11;
        int blk = id & 2047;
        // redundant per-block final reduce of per-tensor mean|w| (deterministic, identical result)
        float ps = 0.f;
        #pragma unroll
        for (int k = 0; k < 8; k++) ps += g_wpart[w_idx][threadIdx.x + k * 256];
        float tot = block_reduce_sum(ps, red);
        float wsc = fmaxf(tot / ((float)D_ * (float)D_), 1e-5f);
        if (blk == 0 && threadIdx.x == 0) g_wscale[w_idx] = wsc;
        const float* w = (w_idx == 0) ? w0 : (w_idx == 1) ? w1 : (w_idx == 2) ? w2 : w3;
        float s = 1.f / wsc;
        size_t base = (size_t)blk * 2048 + threadIdx.x;
        int8_t* q = g_wq[w_idx];
        #pragma unroll
        for (int k = 0; k < 8; k++) {
            float r = rintf(w[base + k * 256] * s);
            r = fminf(fmaxf(r, -1.f), 1.f);
            q[base + k * 256] = (int8_t)r;
        }
    }
}

// ------------------------- 3) int8 GEMM 128x128, BK=128, 3-stage, 2 CTA/SM (R6 mainloop) -------------------------
// which == -1: z = {0,1,2} fused i/f/g (A = xq). which == 3: o-proj (A = yq, C = outp).
__global__ __launch_bounds__(256, 2) void gemm_s8_kernel(int which, float* __restrict__ outp) {
    extern __shared__ __align__(16) int8_t smem[];

    const int w_idx = (which >= 0) ? which : (int)blockIdx.z;
    const int8_t* __restrict__ Aq  = (which == 3) ? g_yq : g_xq;
    const float*  __restrict__ asc = (which == 3) ? g_ysc : g_xsc;
    const int8_t* __restrict__ Wq  = g_wq[w_idx];
    float* __restrict__ C = (which == 3) ? outp
                           : (w_idx == 0 ? g_ilin : (w_idx == 1 ? g_flin : g_glin));
    const float bscale = g_wscale[w_idx];

    const int tid = threadIdx.x;
    const int warp = tid >> 5, lane = tid & 31;
    const int wm = (warp >> 2) * 64;   // 0 or 64
    const int wn = (warp & 3) * 32;    // 0..96
    const int bm = blockIdx.y * BM;
    const int bn = blockIdx.x * BN;

    int acc[4][4][4];
    #pragma unroll
    for (int mi = 0; mi < 4; mi++)
        #pragma unroll
        for (int nj = 0; nj < 4; nj++)
            #pragma unroll
            for (int c = 0; c < 4; c++) acc[mi][nj][c] = 0;

    auto load_stage = [&](int kt, int slot) {
        int8_t* sA = smem + slot * STAGE_BYTES;
        int8_t* sB = sA + A_ST_BYTES;
        int k0 = kt * BK;
        #pragma unroll
        for (int i = 0; i < 4; i++) {        // A: 128 rows x 128B = 1024 cp16
            int id = tid + i * 256;
            int r = id >> 3, cs = (id & 7) * 16;
            cp16(&sA[r * SROW + cs], Aq + (size_t)(bm + r) * D_ + k0 + cs);
        }
        #pragma unroll
        for (int i = 0; i < 4; i++) {        // B: 128 rows x 128B
            int id = tid + i * 256;
            int r = id >> 3, cs = (id & 7) * 16;
            cp16(&sB[r * SROW + cs], Wq + (size_t)(bn + r) * D_ + k0 + cs);
        }
        asm volatile("cp.async.commit_group;\n");
    };

    load_stage(0, 0);
    load_stage(1, 1);

    const int rsel = (lane & 7) + ((lane >> 3) & 1) * 8;
    const int csel_base = (lane >> 4) * 16;

    for (int kt = 0; kt < KT; kt++) {
        int slot = kt % NSTAGE;
        if (kt < KT - 1) asm volatile("cp.async.wait_group 1;\n" ::: "memory");
        else             asm volatile("cp.async.wait_group 0;\n" ::: "memory");
        __syncthreads();

        int nt = kt + 2;
        if (nt < KT) load_stage(nt, nt % NSTAGE);   // writes slot (kt-1)%3, safe after barrier

        int8_t* sA = smem + slot * STAGE_BYTES;
        int8_t* sB = sA + A_ST_BYTES;

        #pragma unroll
        for (int q = 0; q < 4; q++) {               // 4 K-quarters of 32 elems
            int csel = q * 32 + csel_base;

            uint32_t bf[4][2];
            #pragma unroll
            for (int np = 0; np < 2; np++) {
                int row = wn + np * 16 + rsel;
                uint32_t addr = (uint32_t)__cvta_generic_to_shared(&sB[row * SROW + csel]);
                uint32_t t0, t1, t2, t3;
                ldsm_x4(t0, t1, t2, t3, addr);
                bf[np * 2 + 0][0] = t0; bf[np * 2 + 0][1] = t2;
                bf[np * 2 + 1][0] = t1; bf[np * 2 + 1][1] = t3;
            }

            uint32_t af[2][4];
            {
                int row = wm + rsel;
                uint32_t addr = (uint32_t)__cvta_generic_to_shared(&sA[row * SROW + csel]);
                ldsm_x4(af[0][0], af[0][1], af[0][2], af[0][3], addr);
            }
            #pragma unroll
            for (int mi = 0; mi < 4; mi++) {
                if (mi < 3) {
                    int row = wm + (mi + 1) * 16 + rsel;
                    uint32_t addr = (uint32_t)__cvta_generic_to_shared(&sA[row * SROW + csel]);
                    ldsm_x4(af[(mi + 1) & 1][0], af[(mi + 1) & 1][1],
                            af[(mi + 1) & 1][2], af[(mi + 1) & 1][3], addr);
                }
                const uint32_t* a = af[mi & 1];
                #pragma unroll
                for (int nj = 0; nj < 4; nj++) {
                    asm volatile(
                        "mma.sync.aligned.m16n8k32.row.col.s32.s8.s8.s32 "
                        "{%0,%1,%2,%3}, {%4,%5,%6,%7}, {%8,%9}, {%0,%1,%2,%3};\n"
                        : "+r"(acc[mi][nj][0]), "+r"(acc[mi][nj][1]),
                          "+r"(acc[mi][nj][2]), "+r"(acc[mi][nj][3])
                        : "r"(a[0]), "r"(a[1]), "r"(a[2]), "r"(a[3]),
                          "r"(bf[nj][0]), "r"(bf[nj][1]));
                }
            }
        }
    }

    // epilogue: dequant + store
    #pragma unroll
    for (int mi = 0; mi < 4; mi++) {
        int r0 = bm + wm + mi * 16 + (lane >> 2);
        int r1 = r0 + 8;
        float s0 = asc[r0] * bscale;
        float s1 = asc[r1] * bscale;
        #pragma unroll
        for (int nj = 0; nj < 4; nj++) {
            int col = bn + wn + nj * 8 + (lane & 3) * 2;
            float2 v0 = make_float2((float)acc[mi][nj][0] * s0, (float)acc[mi][nj][1] * s0);
            float2 v1 = make_float2((float)acc[mi][nj][2] * s1, (float)acc[mi][nj][3] * s1);
            *(float2*)&C[(size_t)r0 * D_ + col] = v0;
            *(float2*)&C[(size_t)r1 * D_ + col] = v1;
        }
    }
}

// ------------------------- 4) single-pass decoupled-lookback HGRN scan -------------------------
// grid (NCHUNK, B_, NSEG) = 512 blocks, all co-resident. Arithmetic order identical to
// the previous pass1/carry/pass2 chain.
__global__ void scan_lookback_kernel() {
    int chunk = blockIdx.x;
    int d = chunk * 256 + threadIdx.x;
    int b = blockIdx.y;
    int s = blockIdx.z;
    int ch = b * D_ + d;
    int fidx = (b * NCHUNK + chunk) * NSEG + s;

    size_t base = ((size_t)(b * L_ + s * SEGLEN)) * D_ + d;
    // phase 1: local scan (h_local, P)
    float h = 0.f, P = 1.f;
    size_t p = base;
    #pragma unroll 4
    for (int l = 0; l < SEGLEN; l++) {
        float fr = g_flin[p];
        float ir = g_ilin[p];
        float f = sigmoidf_(fr);
        float z = 1.f - f;
        float ig = ir * z * sigmoidf_(z);
        h = fmaf(f, h, ig);
        P *= f;
        p += D_;
    }

    // phase 2: wait for predecessor's inclusive carry
    float c_in = 0.f;
    if (s > 0) {
        if (threadIdx.x == 0) {
            while (((volatile int*)g_flag)[fidx - 1] == 0) { }
        }
        __syncthreads();
        __threadfence();
        c_in = g_carryInc[s - 1][ch];
    }

    // publish own inclusive carry
    g_carryInc[s][ch] = fmaf(P, c_in, h);
    __threadfence();
    __syncthreads();
    if (threadIdx.x == 0) ((volatile int*)g_flag)[fidx] = 1;

    // phase 3: replay segment with carry, write ov (L2-warm reads)
    float h2 = c_in;
    p = base;
    #pragma unroll 4
    for (int l = 0; l < SEGLEN; l++) {
        float fr = g_flin[p];
        float ir = g_ilin[p];
        float f = sigmoidf_(fr);
        float z = 1.f - f;
        float ig = ir * z * sigmoidf_(z);
        h2 = fmaf(f, h2, ig);
        g_ov[p] = h2;
        p += D_;
    }
}

// ------------------------- 5) RMSNorm + swish gate + re-quant y -------------------------
__global__ void gate_kernel(const float* __restrict__ gnw) {
    __shared__ float red[256];
    int t = blockIdx.x;
    size_t base = (size_t)t * D_;
    float gv[8];
    float ss = 0.f;
    #pragma unroll
    for (int k = 0; k < 8; k++) {
        gv[k] = g_glin[base + threadIdx.x + k * 256];
        ss += gv[k] * gv[k];
    }
    float tot = block_reduce_sum(ss, red);
    float rms = rsqrtf(tot / (float)D_ + 1e-5f);

    float amax = 0.f;
    #pragma unroll
    for (int k = 0; k < 8; k++) {
        int d = threadIdx.x + k * 256;
        float ov = g_ov[base + d];
        float y = gv[k] * rms * gnw[d] * ov * sigmoidf_(ov);
        gv[k] = y;
        amax = fmaxf(amax, fabsf(y));
    }
    amax = block_reduce_max(amax, red);
    amax = fmaxf(amax, 1e-5f);
    float s = 127.f / amax;
    if (threadIdx.x == 0) g_ysc[t] = amax / 127.f;
    #pragma unroll
    for (int k = 0; k < 8; k++) {
        float r = rintf(gv[k] * s);
        r = fminf(fmaxf(r, -128.f), 127.f);
        g_yq[base + threadIdx.x + k * 256] = (int8_t)r;
    }
}

// ------------------------- launch -------------------------
extern "C" void kernel_launch(void* const* d_in, const int* in_sizes, int n_in,
                              void* d_out, int out_size) {
    const float* x   = (const float*)d_in[0];
    const float* wi  = (const float*)d_in[1];
    const float* wf  = (const float*)d_in[2];
    const float* wg  = (const float*)d_in[3];
    const float* wo  = (const float*)d_in[4];
    const float* gnw = (const float*)d_in[5];
    float* out = (float*)d_out;

    static bool attr_set = false;
    if (!attr_set) {
        cudaFuncSetAttribute(gemm_s8_kernel, cudaFuncAttributeMaxDynamicSharedMemorySize, SMEM_G);
        attr_set = true;
    }

    wabs_partial_kernel<<<dim3(2048, 4), 256>>>(wi, wf, wg, wo);          // 1 (also zeroes flags)
    quant_all_kernel<<<2 * M_, 256>>>(x, wi, wf, wg, wo);                 // 2 (wscale inline)
    dim3 ggrid(D_ / BN, M_ / BM, 3);   // (16, 64, 3)
    gemm_s8_kernel<<<ggrid, 256, SMEM_G>>>(-1, nullptr);                  // 3
    scan_lookback_kernel<<<dim3(NCHUNK, B_, NSEG), 256>>>();              // 4  <- profiled
    gate_kernel<<<M_, 256>>>(gnw);                                        // 5
    dim3 ogrid(D_ / BN, M_ / BM, 1);
    gemm_s8_kernel<<<ogrid, 256, SMEM_G>>>(3, out);                       // 6
}

// round 15
// speedup vs baseline: 1.1967x; 1.1967x over previous
#include <cuda_runtime.h>
#include <cstdint>
#include <cmath>

// Problem dims (fixed)
#define B_ 4
#define L_ 2048
#define D_ 2048
#define D2 1024             // float2 channel pairs
#define M_ (B_*L_)          // 8192 tokens
#define NSEG 32
#define SEGLEN (L_/NSEG)    // 64

// ---------------- int8 GEMM tiling (R6 config: proven best, tensor-rate-limited) ----------------
#define BM 128
#define BN 128
#define BK 128
#define KT (D_/BK)          // 16
#define NSTAGE 3
#define SROW 144            // 128 data bytes + 16 pad (conflict-free ldsm rows)
#define A_ST_BYTES (BM*SROW)                    // 18432
#define STAGE_BYTES (2*A_ST_BYTES)              // 36864
#define SMEM_G (NSTAGE*STAGE_BYTES)             // 110592 -> 2 CTAs/SM

// ------------------------- scratch (static device globals) -------------------------
__device__ __align__(16) int8_t g_xq[(size_t)M_*D_];
__device__ float  g_xsc[M_];
__device__ __align__(16) int8_t g_wq[4][(size_t)D_*D_];
__device__ float  g_wpart[4][2048];
__device__ float  g_wscale[4];
__device__ float  g_ilin[(size_t)M_*D_];
__device__ float  g_flin[(size_t)M_*D_];
__device__ float  g_glin[(size_t)M_*D_];
__device__ float  g_ov  [(size_t)M_*D_];
__device__ __align__(16) int8_t g_yq[(size_t)M_*D_];
__device__ float  g_ysc[M_];
__device__ float2 g_segP2[NSEG][B_*D2];
__device__ float2 g_segH2[NSEG][B_*D2];
__device__ float2 g_carry2[NSEG][B_*D2];

// ------------------------- helpers -------------------------
__device__ __forceinline__ float block_reduce_sum(float v, float* red) {
    int tid = threadIdx.x;
    red[tid] = v; __syncthreads();
    #pragma unroll
    for (int s = 128; s > 0; s >>= 1) {
        if (tid < s) red[tid] += red[tid + s];
        __syncthreads();
    }
    float r = red[0]; __syncthreads();
    return r;
}
__device__ __forceinline__ float block_reduce_max(float v, float* red) {
    int tid = threadIdx.x;
    red[tid] = v; __syncthreads();
    #pragma unroll
    for (int s = 128; s > 0; s >>= 1) {
        if (tid < s) red[tid] = fmaxf(red[tid], red[tid + s]);
        __syncthreads();
    }
    float r = red[0]; __syncthreads();
    return r;
}
// fast sigmoid: MUFU ex2 + rcp (~1e-6 abs err, fine vs 1e-3 tolerance)
__device__ __forceinline__ float fsig(float x) {
    return __fdividef(1.f, 1.f + __expf(-x));
}

__device__ __forceinline__ void cp16(void* smem, const void* gmem) {
    uint32_t d = (uint32_t)__cvta_generic_to_shared(smem);
    asm volatile("cp.async.cg.shared.global [%0], [%1], 16;\n" :: "r"(d), "l"(gmem));
}
__device__ __forceinline__ void ldsm_x4(uint32_t& r0, uint32_t& r1, uint32_t& r2, uint32_t& r3, uint32_t addr) {
    asm volatile("ldmatrix.sync.aligned.m8n8.x4.shared.b16 {%0,%1,%2,%3}, [%4];\n"
                 : "=r"(r0), "=r"(r1), "=r"(r2), "=r"(r3) : "r"(addr));
}

// ------------------------- 1) weight |.| partial reduction -------------------------
__global__ void wabs_partial_kernel(const float* __restrict__ w0, const float* __restrict__ w1,
                                    const float* __restrict__ w2, const float* __restrict__ w3) {
    __shared__ float red[256];
    const float* w = (blockIdx.y == 0) ? w0 : (blockIdx.y == 1) ? w1 : (blockIdx.y == 2) ? w2 : w3;
    size_t base = (size_t)blockIdx.x * 2048 + threadIdx.x;
    float s = 0.f;
    #pragma unroll
    for (int k = 0; k < 8; k++) s += fabsf(w[base + k * 256]);
    float tot = block_reduce_sum(s, red);
    if (threadIdx.x == 0) g_wpart[blockIdx.y][blockIdx.x] = tot;
}

// ------------------------- 2) fused quant: x rows + all weights (wscale reduced inline) -------------------------
__global__ void quant_all_kernel(const float* __restrict__ x,
                                 const float* __restrict__ w0, const float* __restrict__ w1,
                                 const float* __restrict__ w2, const float* __restrict__ w3) {
    __shared__ float red[256];
    if (blockIdx.x < M_) {
        int t = blockIdx.x;
        const float* row = x + (size_t)t * D_;
        float v[8];
        float amax = 0.f;
        #pragma unroll
        for (int k = 0; k < 8; k++) {
            v[k] = row[threadIdx.x + k * 256];
            amax = fmaxf(amax, fabsf(v[k]));
        }
        amax = block_reduce_max(amax, red);
        amax = fmaxf(amax, 1e-5f);
        float s = 127.f / amax;
        if (threadIdx.x == 0) g_xsc[t] = amax / 127.f;
        int8_t* q = g_xq + (size_t)t * D_;
        #pragma unroll
        for (int k = 0; k < 8; k++) {
            float r = rintf(v[k] * s);
            r = fminf(fmaxf(r, -128.f), 127.f);
            q[threadIdx.x + k * 256] = (int8_t)r;
        }
    } else {
        int id = blockIdx.x - M_;
        int w_idx = id >> 11;
        int blk = id & 2047;
        float ps = 0.f;
        #pragma unroll
        for (int k = 0; k < 8; k++) ps += g_wpart[w_idx][threadIdx.x + k * 256];
        float tot = block_reduce_sum(ps, red);
        float wsc = fmaxf(tot / ((float)D_ * (float)D_), 1e-5f);
        if (blk == 0 && threadIdx.x == 0) g_wscale[w_idx] = wsc;
        const float* w = (w_idx == 0) ? w0 : (w_idx == 1) ? w1 : (w_idx == 2) ? w2 : w3;
        float s = 1.f / wsc;
        size_t base = (size_t)blk * 2048 + threadIdx.x;
        int8_t* q = g_wq[w_idx];
        #pragma unroll
        for (int k = 0; k < 8; k++) {
            float r = rintf(w[base + k * 256] * s);
            r = fminf(fmaxf(r, -1.f), 1.f);
            q[base + k * 256] = (int8_t)r;
        }
    }
}

// ------------------------- 3) int8 GEMM 128x128, BK=128, 3-stage, 2 CTA/SM (R6 mainloop) -------------------------
// which == -1: z = {0,1,2} fused i/f/g (A = xq). which == 3: o-proj (A = yq, C = outp).
__global__ __launch_bounds__(256, 2) void gemm_s8_kernel(int which, float* __restrict__ outp) {
    extern __shared__ __align__(16) int8_t smem[];

    const int w_idx = (which >= 0) ? which : (int)blockIdx.z;
    const int8_t* __restrict__ Aq  = (which == 3) ? g_yq : g_xq;
    const float*  __restrict__ asc = (which == 3) ? g_ysc : g_xsc;
    const int8_t* __restrict__ Wq  = g_wq[w_idx];
    float* __restrict__ C = (which == 3) ? outp
                           : (w_idx == 0 ? g_ilin : (w_idx == 1 ? g_flin : g_glin));
    const float bscale = g_wscale[w_idx];

    const int tid = threadIdx.x;
    const int warp = tid >> 5, lane = tid & 31;
    const int wm = (warp >> 2) * 64;   // 0 or 64
    const int wn = (warp & 3) * 32;    // 0..96
    const int bm = blockIdx.y * BM;
    const int bn = blockIdx.x * BN;

    int acc[4][4][4];
    #pragma unroll
    for (int mi = 0; mi < 4; mi++)
        #pragma unroll
        for (int nj = 0; nj < 4; nj++)
            #pragma unroll
            for (int c = 0; c < 4; c++) acc[mi][nj][c] = 0;

    auto load_stage = [&](int kt, int slot) {
        int8_t* sA = smem + slot * STAGE_BYTES;
        int8_t* sB = sA + A_ST_BYTES;
        int k0 = kt * BK;
        #pragma unroll
        for (int i = 0; i < 4; i++) {        // A: 128 rows x 128B = 1024 cp16
            int id = tid + i * 256;
            int r = id >> 3, cs = (id & 7) * 16;
            cp16(&sA[r * SROW + cs], Aq + (size_t)(bm + r) * D_ + k0 + cs);
        }
        #pragma unroll
        for (int i = 0; i < 4; i++) {        // B: 128 rows x 128B
            int id = tid + i * 256;
            int r = id >> 3, cs = (id & 7) * 16;
            cp16(&sB[r * SROW + cs], Wq + (size_t)(bn + r) * D_ + k0 + cs);
        }
        asm volatile("cp.async.commit_group;\n");
    };

    load_stage(0, 0);
    load_stage(1, 1);

    const int rsel = (lane & 7) + ((lane >> 3) & 1) * 8;
    const int csel_base = (lane >> 4) * 16;

    for (int kt = 0; kt < KT; kt++) {
        int slot = kt % NSTAGE;
        if (kt < KT - 1) asm volatile("cp.async.wait_group 1;\n" ::: "memory");
        else             asm volatile("cp.async.wait_group 0;\n" ::: "memory");
        __syncthreads();

        int nt = kt + 2;
        if (nt < KT) load_stage(nt, nt % NSTAGE);   // writes slot (kt-1)%3, safe after barrier

        int8_t* sA = smem + slot * STAGE_BYTES;
        int8_t* sB = sA + A_ST_BYTES;

        #pragma unroll
        for (int q = 0; q < 4; q++) {               // 4 K-quarters of 32 elems
            int csel = q * 32 + csel_base;

            uint32_t bf[4][2];
            #pragma unroll
            for (int np = 0; np < 2; np++) {
                int row = wn + np * 16 + rsel;
                uint32_t addr = (uint32_t)__cvta_generic_to_shared(&sB[row * SROW + csel]);
                uint32_t t0, t1, t2, t3;
                ldsm_x4(t0, t1, t2, t3, addr);
                bf[np * 2 + 0][0] = t0; bf[np * 2 + 0][1] = t2;
                bf[np * 2 + 1][0] = t1; bf[np * 2 + 1][1] = t3;
            }

            uint32_t af[2][4];
            {
                int row = wm + rsel;
                uint32_t addr = (uint32_t)__cvta_generic_to_shared(&sA[row * SROW + csel]);
                ldsm_x4(af[0][0], af[0][1], af[0][2], af[0][3], addr);
            }
            #pragma unroll
            for (int mi = 0; mi < 4; mi++) {
                if (mi < 3) {
                    int row = wm + (mi + 1) * 16 + rsel;
                    uint32_t addr = (uint32_t)__cvta_generic_to_shared(&sA[row * SROW + csel]);
                    ldsm_x4(af[(mi + 1) & 1][0], af[(mi + 1) & 1][1],
                            af[(mi + 1) & 1][2], af[(mi + 1) & 1][3], addr);
                }
                const uint32_t* a = af[mi & 1];
                #pragma unroll
                for (int nj = 0; nj < 4; nj++) {
                    asm volatile(
                        "mma.sync.aligned.m16n8k32.row.col.s32.s8.s8.s32 "
                        "{%0,%1,%2,%3}, {%4,%5,%6,%7}, {%8,%9}, {%0,%1,%2,%3};\n"
                        : "+r"(acc[mi][nj][0]), "+r"(acc[mi][nj][1]),
                          "+r"(acc[mi][nj][2]), "+r"(acc[mi][nj][3])
                        : "r"(a[0]), "r"(a[1]), "r"(a[2]), "r"(a[3]),
                          "r"(bf[nj][0]), "r"(bf[nj][1]));
                }
            }
        }
    }

    // epilogue: dequant + store
    #pragma unroll
    for (int mi = 0; mi < 4; mi++) {
        int r0 = bm + wm + mi * 16 + (lane >> 2);
        int r1 = r0 + 8;
        float s0 = asc[r0] * bscale;
        float s1 = asc[r1] * bscale;
        #pragma unroll
        for (int nj = 0; nj < 4; nj++) {
            int col = bn + wn + nj * 8 + (lane & 3) * 2;
            float2 v0 = make_float2((float)acc[mi][nj][0] * s0, (float)acc[mi][nj][1] * s0);
            float2 v1 = make_float2((float)acc[mi][nj][2] * s1, (float)acc[mi][nj][3] * s1);
            *(float2*)&C[(size_t)r0 * D_ + col] = v0;
            *(float2*)&C[(size_t)r1 * D_ + col] = v1;
        }
    }
}

// ------------------------- 4) segmented HGRN scan (float2, fast sigmoid) -------------------------
__global__ void scan_pass1_kernel() {
    int d2 = blockIdx.x * 256 + threadIdx.x;    // 0..1023
    int b = blockIdx.y;
    int s = blockIdx.z;
    const float2* __restrict__ F = (const float2*)g_flin;
    const float2* __restrict__ I = (const float2*)g_ilin;
    size_t base = ((size_t)(b * L_ + s * SEGLEN)) * D2 + d2;
    float2 h = make_float2(0.f, 0.f);
    float2 P = make_float2(1.f, 1.f);
    #pragma unroll 4
    for (int l = 0; l < SEGLEN; l++) {
        float2 fr = F[base];
        float2 ir = I[base];
        float f0 = fsig(fr.x), f1 = fsig(fr.y);
        float z0 = 1.f - f0,   z1 = 1.f - f1;
        h.x = fmaf(f0, h.x, ir.x * z0 * fsig(z0));
        h.y = fmaf(f1, h.y, ir.y * z1 * fsig(z1));
        P.x *= f0; P.y *= f1;
        base += D2;
    }
    int ch = b * D2 + d2;
    g_segP2[s][ch] = P;
    g_segH2[s][ch] = h;
}

__global__ void scan_carry_kernel() {
    int ch = blockIdx.x * 256 + threadIdx.x;    // 0..4095
    float2 c = make_float2(0.f, 0.f);
    #pragma unroll
    for (int s = 0; s < NSEG; s++) {
        g_carry2[s][ch] = c;
        float2 P = g_segP2[s][ch];
        float2 H = g_segH2[s][ch];
        c.x = fmaf(P.x, c.x, H.x);
        c.y = fmaf(P.y, c.y, H.y);
    }
}

__global__ void scan_pass2_kernel() {
    int d2 = blockIdx.x * 256 + threadIdx.x;
    int b = blockIdx.y;
    int s = blockIdx.z;
    const float2* __restrict__ F = (const float2*)g_flin;
    const float2* __restrict__ I = (const float2*)g_ilin;
    float2* __restrict__ OV = (float2*)g_ov;
    int ch = b * D2 + d2;
    size_t base = ((size_t)(b * L_ + s * SEGLEN)) * D2 + d2;
    float2 h = g_carry2[s][ch];
    #pragma unroll 4
    for (int l = 0; l < SEGLEN; l++) {
        float2 fr = F[base];
        float2 ir = I[base];
        float f0 = fsig(fr.x), f1 = fsig(fr.y);
        float z0 = 1.f - f0,   z1 = 1.f - f1;
        h.x = fmaf(f0, h.x, ir.x * z0 * fsig(z0));
        h.y = fmaf(f1, h.y, ir.y * z1 * fsig(z1));
        OV[base] = h;
        base += D2;
    }
}

// ------------------------- 5) RMSNorm + swish gate + re-quant y (float2, fast sigmoid) -------------------------
__global__ void gate_kernel(const float* __restrict__ gnw) {
    __shared__ float red[256];
    int t = blockIdx.x;
    const float2* __restrict__ G  = (const float2*)g_glin;
    const float2* __restrict__ OV = (const float2*)g_ov;
    const float2* __restrict__ W  = (const float2*)gnw;
    size_t base2 = (size_t)t * D2;
    float2 gv[4];
    float ss = 0.f;
    #pragma unroll
    for (int k = 0; k < 4; k++) {
        gv[k] = G[base2 + threadIdx.x + k * 256];
        ss += gv[k].x * gv[k].x + gv[k].y * gv[k].y;
    }
    float tot = block_reduce_sum(ss, red);
    float rms = rsqrtf(tot / (float)D_ + 1e-5f);

    float2 yv[4];
    float amax = 0.f;
    #pragma unroll
    for (int k = 0; k < 4; k++) {
        int d2 = threadIdx.x + k * 256;
        float2 ov = OV[base2 + d2];
        float2 w  = W[d2];
        float y0 = gv[k].x * rms * w.x * ov.x * fsig(ov.x);
        float y1 = gv[k].y * rms * w.y * ov.y * fsig(ov.y);
        yv[k] = make_float2(y0, y1);
        amax = fmaxf(amax, fmaxf(fabsf(y0), fabsf(y1)));
    }
    amax = block_reduce_max(amax, red);
    amax = fmaxf(amax, 1e-5f);
    float s = 127.f / amax;
    if (threadIdx.x == 0) g_ysc[t] = amax / 127.f;
    #pragma unroll
    for (int k = 0; k < 4; k++) {
        int d2 = threadIdx.x + k * 256;
        float r0 = fminf(fmaxf(rintf(yv[k].x * s), -128.f), 127.f);
        float r1 = fminf(fmaxf(rintf(yv[k].y * s), -128.f), 127.f);
        char2 pk; pk.x = (int8_t)r0; pk.y = (int8_t)r1;
        *(char2*)&g_yq[(size_t)t * D_ + d2 * 2] = pk;
    }
}

// ------------------------- launch -------------------------
extern "C" void kernel_launch(void* const* d_in, const int* in_sizes, int n_in,
                              void* d_out, int out_size) {
    const float* x   = (const float*)d_in[0];
    const float* wi  = (const float*)d_in[1];
    const float* wf  = (const float*)d_in[2];
    const float* wg  = (const float*)d_in[3];
    const float* wo  = (const float*)d_in[4];
    const float* gnw = (const float*)d_in[5];
    float* out = (float*)d_out;

    static bool attr_set = false;
    if (!attr_set) {
        cudaFuncSetAttribute(gemm_s8_kernel, cudaFuncAttributeMaxDynamicSharedMemorySize, SMEM_G);
        attr_set = true;
    }

    wabs_partial_kernel<<<dim3(2048, 4), 256>>>(wi, wf, wg, wo);          // 1
    quant_all_kernel<<<2 * M_, 256>>>(x, wi, wf, wg, wo);                 // 2 (wscale inline)
    dim3 ggrid(D_ / BN, M_ / BM, 3);   // (16, 64, 3)
    gemm_s8_kernel<<<ggrid, 256, SMEM_G>>>(-1, nullptr);                  // 3
    scan_pass1_kernel<<<dim3(D2 / 256, B_, NSEG), 256>>>();               // 4  <- profiled
    scan_carry_kernel<<<(B_ * D2) / 256, 256>>>();                        // 5
    scan_pass2_kernel<<<dim3(D2 / 256, B_, NSEG), 256>>>();               // 6
    gate_kernel<<<M_, 256>>>(gnw);                                        // 7
    dim3 ogrid(D_ / BN, M_ / BM, 1);
    gemm_s8_kernel<<<ogrid, 256, SMEM_G>>>(3, out);                       // 8
}

// round 16
// speedup vs baseline: 1.1978x; 1.0009x over previous
#include <cuda_runtime.h>
#include <cstdint>
#include <cmath>

// Problem dims (fixed)
#define B_ 4
#define L_ 2048
#define D_ 2048
#define D2 1024             // float2 channel pairs
#define M_ (B_*L_)          // 8192 tokens
#define NSEG 32
#define SEGLEN (L_/NSEG)    // 64

// ---------------- int8 GEMM tiling (R6 config: proven best, tensor-rate-limited) ----------------
#define BM 128
#define BN 128
#define BK 128
#define KT (D_/BK)          // 16
#define NSTAGE 3
#define SROW 144            // 128 data bytes + 16 pad (conflict-free ldsm rows)
#define A_ST_BYTES (BM*SROW)                    // 18432
#define STAGE_BYTES (2*A_ST_BYTES)              // 36864
#define SMEM_G (NSTAGE*STAGE_BYTES)             // 110592 -> 2 CTAs/SM

// ------------------------- scratch (static device globals) -------------------------
__device__ __align__(16) int8_t g_xq[(size_t)M_*D_];
__device__ float  g_xsc[M_];
__device__ __align__(16) int8_t g_wq[4][(size_t)D_*D_];
__device__ float  g_wpart[4][2048];
__device__ float  g_wscale[4];
__device__ float  g_ilin[(size_t)M_*D_];
__device__ float  g_flin[(size_t)M_*D_];
__device__ float  g_glin[(size_t)M_*D_];
__device__ float  g_ov  [(size_t)M_*D_];
__device__ __align__(16) int8_t g_yq[(size_t)M_*D_];
__device__ float  g_ysc[M_];
__device__ float2 g_segP2[NSEG][B_*D2];
__device__ float2 g_segH2[NSEG][B_*D2];
__device__ float2 g_carry2[NSEG][B_*D2];

// ------------------------- helpers -------------------------
__device__ __forceinline__ float block_reduce_sum(float v, float* red) {
    int tid = threadIdx.x;
    red[tid] = v; __syncthreads();
    #pragma unroll
    for (int s = 128; s > 0; s >>= 1) {
        if (tid < s) red[tid] += red[tid + s];
        __syncthreads();
    }
    float r = red[0]; __syncthreads();
    return r;
}
__device__ __forceinline__ float block_reduce_max(float v, float* red) {
    int tid = threadIdx.x;
    red[tid] = v; __syncthreads();
    #pragma unroll
    for (int s = 128; s > 0; s >>= 1) {
        if (tid < s) red[tid] = fmaxf(red[tid], red[tid + s]);
        __syncthreads();
    }
    float r = red[0]; __syncthreads();
    return r;
}
// fast sigmoid: MUFU ex2 + rcp (~1e-6 abs err, fine vs 1e-3 tolerance)
__device__ __forceinline__ float fsig(float x) {
    return __fdividef(1.f, 1.f + __expf(-x));
}

__device__ __forceinline__ void cp16(void* smem, const void* gmem) {
    uint32_t d = (uint32_t)__cvta_generic_to_shared(smem);
    asm volatile("cp.async.cg.shared.global [%0], [%1], 16;\n" :: "r"(d), "l"(gmem));
}
__device__ __forceinline__ void ldsm_x4(uint32_t& r0, uint32_t& r1, uint32_t& r2, uint32_t& r3, uint32_t addr) {
    asm volatile("ldmatrix.sync.aligned.m8n8.x4.shared.b16 {%0,%1,%2,%3}, [%4];\n"
                 : "=r"(r0), "=r"(r1), "=r"(r2), "=r"(r3) : "r"(addr));
}

// ------------------------- 1) weight |.| partial reduction -------------------------
__global__ void wabs_partial_kernel(const float* __restrict__ w0, const float* __restrict__ w1,
                                    const float* __restrict__ w2, const float* __restrict__ w3) {
    __shared__ float red[256];
    const float* w = (blockIdx.y == 0) ? w0 : (blockIdx.y == 1) ? w1 : (blockIdx.y == 2) ? w2 : w3;
    size_t base = (size_t)blockIdx.x * 2048 + threadIdx.x;
    float s = 0.f;
    #pragma unroll
    for (int k = 0; k < 8; k++) s += fabsf(w[base + k * 256]);
    float tot = block_reduce_sum(s, red);
    if (threadIdx.x == 0) g_wpart[blockIdx.y][blockIdx.x] = tot;
}

// ------------------------- 2) fused quant: x rows + all weights (wscale reduced inline) -------------------------
__global__ void quant_all_kernel(const float* __restrict__ x,
                                 const float* __restrict__ w0, const float* __restrict__ w1,
                                 const float* __restrict__ w2, const float* __restrict__ w3) {
    __shared__ float red[256];
    if (blockIdx.x < M_) {
        int t = blockIdx.x;
        const float* row = x + (size_t)t * D_;
        float v[8];
        float amax = 0.f;
        #pragma unroll
        for (int k = 0; k < 8; k++) {
            v[k] = row[threadIdx.x + k * 256];
            amax = fmaxf(amax, fabsf(v[k]));
        }
        amax = block_reduce_max(amax, red);
        amax = fmaxf(amax, 1e-5f);
        float s = 127.f / amax;
        if (threadIdx.x == 0) g_xsc[t] = amax / 127.f;
        int8_t* q = g_xq + (size_t)t * D_;
        #pragma unroll
        for (int k = 0; k < 8; k++) {
            float r = rintf(v[k] * s);
            r = fminf(fmaxf(r, -128.f), 127.f);
            q[threadIdx.x + k * 256] = (int8_t)r;
        }
    } else {
        int id = blockIdx.x - M_;
        int w_idx = id >> 11;
        int blk = id & 2047;
        float ps = 0.f;
        #pragma unroll
        for (int k = 0; k < 8; k++) ps += g_wpart[w_idx][threadIdx.x + k * 256];
        float tot = block_reduce_sum(ps, red);
        float wsc = fmaxf(tot / ((float)D_ * (float)D_), 1e-5f);
        if (blk == 0 && threadIdx.x == 0) g_wscale[w_idx] = wsc;
        const float* w = (w_idx == 0) ? w0 : (w_idx == 1) ? w1 : (w_idx == 2) ? w2 : w3;
        float s = 1.f / wsc;
        size_t base = (size_t)blk * 2048 + threadIdx.x;
        int8_t* q = g_wq[w_idx];
        #pragma unroll
        for (int k = 0; k < 8; k++) {
            float r = rintf(w[base + k * 256] * s);
            r = fminf(fmaxf(r, -1.f), 1.f);
            q[base + k * 256] = (int8_t)r;
        }
    }
}

// ------------------------- 3) int8 GEMM 128x128, BK=128, 3-stage, 2 CTA/SM (R6 mainloop) -------------------------
// which == -1: z = {0,1,2} fused i/f/g (A = xq). which == 3: o-proj (A = yq, C = outp).
__global__ __launch_bounds__(256, 2) void gemm_s8_kernel(int which, float* __restrict__ outp) {
    extern __shared__ __align__(16) int8_t smem[];

    const int w_idx = (which >= 0) ? which : (int)blockIdx.z;
    const int8_t* __restrict__ Aq  = (which == 3) ? g_yq : g_xq;
    const float*  __restrict__ asc = (which == 3) ? g_ysc : g_xsc;
    const int8_t* __restrict__ Wq  = g_wq[w_idx];
    float* __restrict__ C = (which == 3) ? outp
                           : (w_idx == 0 ? g_ilin : (w_idx == 1 ? g_flin : g_glin));
    const float bscale = g_wscale[w_idx];

    const int tid = threadIdx.x;
    const int warp = tid >> 5, lane = tid & 31;
    const int wm = (warp >> 2) * 64;   // 0 or 64
    const int wn = (warp & 3) * 32;    // 0..96
    const int bm = blockIdx.y * BM;
    const int bn = blockIdx.x * BN;

    int acc[4][4][4];
    #pragma unroll
    for (int mi = 0; mi < 4; mi++)
        #pragma unroll
        for (int nj = 0; nj < 4; nj++)
            #pragma unroll
            for (int c = 0; c < 4; c++) acc[mi][nj][c] = 0;

    auto load_stage = [&](int kt, int slot) {
        int8_t* sA = smem + slot * STAGE_BYTES;
        int8_t* sB = sA + A_ST_BYTES;
        int k0 = kt * BK;
        #pragma unroll
        for (int i = 0; i < 4; i++) {        // A: 128 rows x 128B = 1024 cp16
            int id = tid + i * 256;
            int r = id >> 3, cs = (id & 7) * 16;
            cp16(&sA[r * SROW + cs], Aq + (size_t)(bm + r) * D_ + k0 + cs);
        }
        #pragma unroll
        for (int i = 0; i < 4; i++) {        // B: 128 rows x 128B
            int id = tid + i * 256;
            int r = id >> 3, cs = (id & 7) * 16;
            cp16(&sB[r * SROW + cs], Wq + (size_t)(bn + r) * D_ + k0 + cs);
        }
        asm volatile("cp.async.commit_group;\n");
    };

    load_stage(0, 0);
    load_stage(1, 1);

    const int rsel = (lane & 7) + ((lane >> 3) & 1) * 8;
    const int csel_base = (lane >> 4) * 16;

    for (int kt = 0; kt < KT; kt++) {
        int slot = kt % NSTAGE;
        if (kt < KT - 1) asm volatile("cp.async.wait_group 1;\n" ::: "memory");
        else             asm volatile("cp.async.wait_group 0;\n" ::: "memory");
        __syncthreads();

        int nt = kt + 2;
        if (nt < KT) load_stage(nt, nt % NSTAGE);   // writes slot (kt-1)%3, safe after barrier

        int8_t* sA = smem + slot * STAGE_BYTES;
        int8_t* sB = sA + A_ST_BYTES;

        #pragma unroll
        for (int q = 0; q < 4; q++) {               // 4 K-quarters of 32 elems
            int csel = q * 32 + csel_base;

            uint32_t bf[4][2];
            #pragma unroll
            for (int np = 0; np < 2; np++) {
                int row = wn + np * 16 + rsel;
                uint32_t addr = (uint32_t)__cvta_generic_to_shared(&sB[row * SROW + csel]);
                uint32_t t0, t1, t2, t3;
                ldsm_x4(t0, t1, t2, t3, addr);
                bf[np * 2 + 0][0] = t0; bf[np * 2 + 0][1] = t2;
                bf[np * 2 + 1][0] = t1; bf[np * 2 + 1][1] = t3;
            }

            uint32_t af[2][4];
            {
                int row = wm + rsel;
                uint32_t addr = (uint32_t)__cvta_generic_to_shared(&sA[row * SROW + csel]);
                ldsm_x4(af[0][0], af[0][1], af[0][2], af[0][3], addr);
            }
            #pragma unroll
            for (int mi = 0; mi < 4; mi++) {
                if (mi < 3) {
                    int row = wm + (mi + 1) * 16 + rsel;
                    uint32_t addr = (uint32_t)__cvta_generic_to_shared(&sA[row * SROW + csel]);
                    ldsm_x4(af[(mi + 1) & 1][0], af[(mi + 1) & 1][1],
                            af[(mi + 1) & 1][2], af[(mi + 1) & 1][3], addr);
                }
                const uint32_t* a = af[mi & 1];
                #pragma unroll
                for (int nj = 0; nj < 4; nj++) {
                    asm volatile(
                        "mma.sync.aligned.m16n8k32.row.col.s32.s8.s8.s32 "
                        "{%0,%1,%2,%3}, {%4,%5,%6,%7}, {%8,%9}, {%0,%1,%2,%3};\n"
                        : "+r"(acc[mi][nj][0]), "+r"(acc[mi][nj][1]),
                          "+r"(acc[mi][nj][2]), "+r"(acc[mi][nj][3])
                        : "r"(a[0]), "r"(a[1]), "r"(a[2]), "r"(a[3]),
                          "r"(bf[nj][0]), "r"(bf[nj][1]));
                }
            }
        }
    }

    // epilogue: dequant + store
    #pragma unroll
    for (int mi = 0; mi < 4; mi++) {
        int r0 = bm + wm + mi * 16 + (lane >> 2);
        int r1 = r0 + 8;
        float s0 = asc[r0] * bscale;
        float s1 = asc[r1] * bscale;
        #pragma unroll
        for (int nj = 0; nj < 4; nj++) {
            int col = bn + wn + nj * 8 + (lane & 3) * 2;
            float2 v0 = make_float2((float)acc[mi][nj][0] * s0, (float)acc[mi][nj][1] * s0);
            float2 v1 = make_float2((float)acc[mi][nj][2] * s1, (float)acc[mi][nj][3] * s1);
            *(float2*)&C[(size_t)r0 * D_ + col] = v0;
            *(float2*)&C[(size_t)r1 * D_ + col] = v1;
        }
    }
}

// ------------------------- 4) segmented HGRN scan (float2, fast sigmoid) -------------------------
__global__ void scan_pass1_kernel() {
    int d2 = blockIdx.x * 256 + threadIdx.x;    // 0..1023
    int b = blockIdx.y;
    int s = blockIdx.z;
    const float2* __restrict__ F = (const float2*)g_flin;
    const float2* __restrict__ I = (const float2*)g_ilin;
    size_t base = ((size_t)(b * L_ + s * SEGLEN)) * D2 + d2;
    float2 h = make_float2(0.f, 0.f);
    float2 P = make_float2(1.f, 1.f);
    #pragma unroll 4
    for (int l = 0; l < SEGLEN; l++) {
        float2 fr = F[base];
        float2 ir = I[base];
        float f0 = fsig(fr.x), f1 = fsig(fr.y);
        float z0 = 1.f - f0,   z1 = 1.f - f1;
        h.x = fmaf(f0, h.x, ir.x * z0 * fsig(z0));
        h.y = fmaf(f1, h.y, ir.y * z1 * fsig(z1));
        P.x *= f0; P.y *= f1;
        base += D2;
    }
    int ch = b * D2 + d2;
    g_segP2[s][ch] = P;
    g_segH2[s][ch] = h;
}

__global__ void scan_carry_kernel() {
    int ch = blockIdx.x * 256 + threadIdx.x;    // 0..4095
    float2 c = make_float2(0.f, 0.f);
    #pragma unroll
    for (int s = 0; s < NSEG; s++) {
        g_carry2[s][ch] = c;
        float2 P = g_segP2[s][ch];
        float2 H = g_segH2[s][ch];
        c.x = fmaf(P.x, c.x, H.x);
        c.y = fmaf(P.y, c.y, H.y);
    }
}

__global__ void scan_pass2_kernel() {
    int d2 = blockIdx.x * 256 + threadIdx.x;
    int b = blockIdx.y;
    int s = blockIdx.z;
    const float2* __restrict__ F = (const float2*)g_flin;
    const float2* __restrict__ I = (const float2*)g_ilin;
    float2* __restrict__ OV = (float2*)g_ov;
    int ch = b * D2 + d2;
    size_t base = ((size_t)(b * L_ + s * SEGLEN)) * D2 + d2;
    float2 h = g_carry2[s][ch];
    #pragma unroll 4
    for (int l = 0; l < SEGLEN; l++) {
        float2 fr = F[base];
        float2 ir = I[base];
        float f0 = fsig(fr.x), f1 = fsig(fr.y);
        float z0 = 1.f - f0,   z1 = 1.f - f1;
        h.x = fmaf(f0, h.x, ir.x * z0 * fsig(z0));
        h.y = fmaf(f1, h.y, ir.y * z1 * fsig(z1));
        OV[base] = h;
        base += D2;
    }
}

// ------------------------- 5) RMSNorm + swish gate + re-quant y (float2, fast sigmoid) -------------------------
__global__ void gate_kernel(const float* __restrict__ gnw) {
    __shared__ float red[256];
    int t = blockIdx.x;
    const float2* __restrict__ G  = (const float2*)g_glin;
    const float2* __restrict__ OV = (const float2*)g_ov;
    const float2* __restrict__ W  = (const float2*)gnw;
    size_t base2 = (size_t)t * D2;
    float2 gv[4];
    float ss = 0.f;
    #pragma unroll
    for (int k = 0; k < 4; k++) {
        gv[k] = G[base2 + threadIdx.x + k * 256];
        ss += gv[k].x * gv[k].x + gv[k].y * gv[k].y;
    }
    float tot = block_reduce_sum(ss, red);
    float rms = rsqrtf(tot / (float)D_ + 1e-5f);

    float2 yv[4];
    float amax = 0.f;
    #pragma unroll
    for (int k = 0; k < 4; k++) {
        int d2 = threadIdx.x + k * 256;
        float2 ov = OV[base2 + d2];
        float2 w  = W[d2];
        float y0 = gv[k].x * rms * w.x * ov.x * fsig(ov.x);
        float y1 = gv[k].y * rms * w.y * ov.y * fsig(ov.y);
        yv[k] = make_float2(y0, y1);
        amax = fmaxf(amax, fmaxf(fabsf(y0), fabsf(y1)));
    }
    amax = block_reduce_max(amax, red);
    amax = fmaxf(amax, 1e-5f);
    float s = 127.f / amax;
    if (threadIdx.x == 0) g_ysc[t] = amax / 127.f;
    #pragma unroll
    for (int k = 0; k < 4; k++) {
        int d2 = threadIdx.x + k * 256;
        float r0 = fminf(fmaxf(rintf(yv[k].x * s), -128.f), 127.f);
        float r1 = fminf(fmaxf(rintf(yv[k].y * s), -128.f), 127.f);
        char2 pk; pk.x = (int8_t)r0; pk.y = (int8_t)r1;
        *(char2*)&g_yq[(size_t)t * D_ + d2 * 2] = pk;
    }
}

// ------------------------- launch -------------------------
extern "C" void kernel_launch(void* const* d_in, const int* in_sizes, int n_in,
                              void* d_out, int out_size) {
    const float* x   = (const float*)d_in[0];
    const float* wi  = (const float*)d_in[1];
    const float* wf  = (const float*)d_in[2];
    const float* wg  = (const float*)d_in[3];
    const float* wo  = (const float*)d_in[4];
    const float* gnw = (const float*)d_in[5];
    float* out = (float*)d_out;

    static bool attr_set = false;
    if (!attr_set) {
        cudaFuncSetAttribute(gemm_s8_kernel, cudaFuncAttributeMaxDynamicSharedMemorySize, SMEM_G);
        attr_set = true;
    }

    wabs_partial_kernel<<<dim3(2048, 4), 256>>>(wi, wf, wg, wo);          // 1
    quant_all_kernel<<<2 * M_, 256>>>(x, wi, wf, wg, wo);                 // 2 (wscale inline)
    dim3 ggrid(D_ / BN, M_ / BM, 3);   // (16, 64, 3)
    gemm_s8_kernel<<<ggrid, 256, SMEM_G>>>(-1, nullptr);                  // 3
    scan_pass1_kernel<<<dim3(D2 / 256, B_, NSEG), 256>>>();               // 4  <- profiled
    scan_carry_kernel<<<(B_ * D2) / 256, 256>>>();                        // 5
    scan_pass2_kernel<<<dim3(D2 / 256, B_, NSEG), 256>>>();               // 6
    gate_kernel<<<M_, 256>>>(gnw);                                        // 7
    dim3 ogrid(D_ / BN, M_ / BM, 1);
    gemm_s8_kernel<<<ogrid, 256, SMEM_G>>>(3, out);                       // 8
}